// round 1
// baseline (speedup 1.0000x reference)
#include <cuda_runtime.h>
#include <math.h>

// Problem shapes (fixed by the dataset)
#define BB  2
#define NC  512
#define NF  8192
#define MM  8192
#define TILE 2048
#define NT  256
#define EPSF 1e-12f

// ---------------- scratch (__device__ globals; no allocation allowed) ----------------
__device__ float g_nt[BB * NF * 3];        // gathered nearest target per fine point
__device__ float g_pf[BB][32][4];          // fine blocks: sum sqrt(d1), sum zf^2, sum znt^2, sum ydiff^2
__device__ float g_pt[BB][32][2];          // target blocks: sum sqrt(min over fine), sum sqrt(min over coarse)
__device__ float g_pc[BB][2];              // coarse blocks: sum sqrt(d1 coarse)
__device__ float g_pv[BB][32][2];          // volume partials: fine, new_target

// Deterministic in-block tree reduction
__device__ __forceinline__ float blockSum(float v, float* sh) {
    int t = threadIdx.x;
    sh[t] = v;
    __syncthreads();
#pragma unroll
    for (int s = NT / 2; s > 0; s >>= 1) {
        if (t < s) sh[t] += sh[t + s];
        __syncthreads();
    }
    float r = sh[0];
    __syncthreads();
    return r;
}

// Fused nearest-neighbor kernel.
// grid = (66, BB). blockIdx.x: [0,32) fine->target (argmin+gather), [32,64) target->{fine,coarse}, [64,66) coarse->target
__global__ void __launch_bounds__(NT) nn_kernel(const float* __restrict__ sc,
                                                const float* __restrict__ sf,
                                                const float* __restrict__ tp)
{
    __shared__ float s0[TILE], s1[TILE], s2[TILE], sq[TILE];
    __shared__ float sred[NT];

    const int b   = blockIdx.y;
    const int bx  = blockIdx.x;
    const int tid = threadIdx.x;

    const float* tgt = tp + (size_t)b * MM * 3;
    const float* fin = sf + (size_t)b * NF * 3;
    const float* crs = sc + (size_t)b * NC * 3;

    if (bx < 32) {
        // ---- fine -> target: argmin + gather + stats ----
        const int qi = bx * NT + tid;
        const float qx = fin[qi * 3 + 0];
        const float qy = fin[qi * 3 + 1];
        const float qz = fin[qi * 3 + 2];
        const float qq = qx * qx + qy * qy + qz * qz;

        float bA = 3.0e38f, bB = 3.0e38f;
        int   jA = 0,       jB = 0;

        for (int t0 = 0; t0 < MM; t0 += TILE) {
            for (int k = tid; k < TILE; k += NT) {
                const int j = t0 + k;
                const float y0 = tgt[j * 3 + 0];
                const float y1 = tgt[j * 3 + 1];
                const float y2 = tgt[j * 3 + 2];
                s0[k] = y0; s1[k] = y1; s2[k] = y2;
                sq[k] = y0 * y0 + y1 * y1 + y2 * y2;
            }
            __syncthreads();
#pragma unroll 8
            for (int k = 0; k < TILE; k += 2) {
                const float xyA = fmaf(qz, s2[k],     fmaf(qy, s1[k],     qx * s0[k]));
                const float tA  = fmaf(-2.0f, xyA, sq[k]);
                if (tA < bA) { bA = tA; jA = t0 + k; }
                const float xyB = fmaf(qz, s2[k + 1], fmaf(qy, s1[k + 1], qx * s0[k + 1]));
                const float tB  = fmaf(-2.0f, xyB, sq[k + 1]);
                if (tB < bB) { bB = tB; jB = t0 + k + 1; }
            }
            __syncthreads();
        }
        float best = bA; int jbest = jA;
        if (bB < bA) { best = bB; jbest = jB; }

        const float d  = fmaxf(qq + best, 0.0f);
        const float d1 = sqrtf(fmaxf(d, EPSF));

        const float nx = tgt[jbest * 3 + 0];
        const float ny = tgt[jbest * 3 + 1];
        const float nz = tgt[jbest * 3 + 2];
        const int o = (b * NF + qi) * 3;
        g_nt[o + 0] = nx; g_nt[o + 1] = ny; g_nt[o + 2] = nz;

        const float yd = qy - ny;
        const float r0 = blockSum(d1,      sred);
        const float r1 = blockSum(qz * qz, sred);
        const float r2 = blockSum(nz * nz, sred);
        const float r3 = blockSum(yd * yd, sred);
        if (tid == 0) {
            g_pf[b][bx][0] = r0; g_pf[b][bx][1] = r1;
            g_pf[b][bx][2] = r2; g_pf[b][bx][3] = r3;
        }
    } else if (bx < 64) {
        // ---- target -> fine (min) and target -> coarse (min) ----
        const int qj = (bx - 32) * NT + tid;
        const float qx = tgt[qj * 3 + 0];
        const float qy = tgt[qj * 3 + 1];
        const float qz = tgt[qj * 3 + 2];
        const float qq = qx * qx + qy * qy + qz * qz;

        float mfA = 3.0e38f, mfB = 3.0e38f;
        for (int t0 = 0; t0 < NF; t0 += TILE) {
            for (int k = tid; k < TILE; k += NT) {
                const int j = t0 + k;
                const float y0 = fin[j * 3 + 0];
                const float y1 = fin[j * 3 + 1];
                const float y2 = fin[j * 3 + 2];
                s0[k] = y0; s1[k] = y1; s2[k] = y2;
                sq[k] = y0 * y0 + y1 * y1 + y2 * y2;
            }
            __syncthreads();
#pragma unroll 8
            for (int k = 0; k < TILE; k += 2) {
                const float xyA = fmaf(qz, s2[k],     fmaf(qy, s1[k],     qx * s0[k]));
                mfA = fminf(mfA, fmaf(-2.0f, xyA, sq[k]));
                const float xyB = fmaf(qz, s2[k + 1], fmaf(qy, s1[k + 1], qx * s0[k + 1]));
                mfB = fminf(mfB, fmaf(-2.0f, xyB, sq[k + 1]));
            }
            __syncthreads();
        }
        const float minF = fminf(mfA, mfB);

        // coarse tile (NC = 512 fits in one tile)
        for (int k = tid; k < NC; k += NT) {
            const float y0 = crs[k * 3 + 0];
            const float y1 = crs[k * 3 + 1];
            const float y2 = crs[k * 3 + 2];
            s0[k] = y0; s1[k] = y1; s2[k] = y2;
            sq[k] = y0 * y0 + y1 * y1 + y2 * y2;
        }
        __syncthreads();
        float mcA = 3.0e38f, mcB = 3.0e38f;
#pragma unroll 8
        for (int k = 0; k < NC; k += 2) {
            const float xyA = fmaf(qz, s2[k],     fmaf(qy, s1[k],     qx * s0[k]));
            mcA = fminf(mcA, fmaf(-2.0f, xyA, sq[k]));
            const float xyB = fmaf(qz, s2[k + 1], fmaf(qy, s1[k + 1], qx * s0[k + 1]));
            mcB = fminf(mcB, fmaf(-2.0f, xyB, sq[k + 1]));
        }
        __syncthreads();
        const float minC = fminf(mcA, mcB);

        const float d2f = sqrtf(fmaxf(fmaxf(qq + minF, 0.0f), EPSF));
        const float d2c = sqrtf(fmaxf(fmaxf(qq + minC, 0.0f), EPSF));
        const float r0 = blockSum(d2f, sred);
        const float r1 = blockSum(d2c, sred);
        if (tid == 0) { g_pt[b][bx - 32][0] = r0; g_pt[b][bx - 32][1] = r1; }
    } else {
        // ---- coarse -> target (min) ----
        const int ci = (bx - 64) * NT + tid;
        const float qx = crs[ci * 3 + 0];
        const float qy = crs[ci * 3 + 1];
        const float qz = crs[ci * 3 + 2];
        const float qq = qx * qx + qy * qy + qz * qz;

        float mA = 3.0e38f, mB = 3.0e38f;
        for (int t0 = 0; t0 < MM; t0 += TILE) {
            for (int k = tid; k < TILE; k += NT) {
                const int j = t0 + k;
                const float y0 = tgt[j * 3 + 0];
                const float y1 = tgt[j * 3 + 1];
                const float y2 = tgt[j * 3 + 2];
                s0[k] = y0; s1[k] = y1; s2[k] = y2;
                sq[k] = y0 * y0 + y1 * y1 + y2 * y2;
            }
            __syncthreads();
#pragma unroll 8
            for (int k = 0; k < TILE; k += 2) {
                const float xyA = fmaf(qz, s2[k],     fmaf(qy, s1[k],     qx * s0[k]));
                mA = fminf(mA, fmaf(-2.0f, xyA, sq[k]));
                const float xyB = fmaf(qz, s2[k + 1], fmaf(qy, s1[k + 1], qx * s0[k + 1]));
                mB = fminf(mB, fmaf(-2.0f, xyB, sq[k + 1]));
            }
            __syncthreads();
        }
        const float d1c = sqrtf(fmaxf(fmaxf(qq + fminf(mA, mB), 0.0f), EPSF));
        const float r0 = blockSum(d1c, sred);
        if (tid == 0) g_pc[b][bx - 64] = r0;
    }
}

// Wedge-product volume partials for source_fine and gathered new_target.
// grid = (32, BB), one thread per consecutive triple.
__global__ void __launch_bounds__(NT) volume_kernel(const float* __restrict__ sf)
{
    __shared__ float sred[NT];
    const int b   = blockIdx.y;
    const int bx  = blockIdx.x;
    const int tid = threadIdx.x;
    const int i   = bx * NT + tid;

    float vf = 0.0f, vn = 0.0f;
    if (i < NF - 2) {
        const float* p = sf + (size_t)b * NF * 3 + (size_t)i * 3;
        float a0 = p[0], a1 = p[1], a2 = p[2];
        float e0 = p[3], e1 = p[4], e2 = p[5];
        float c0 = p[6], c1 = p[7], c2 = p[8];
        float cx = a1 * e2 - a2 * e1;
        float cy = a2 * e0 - a0 * e2;
        float cz = a0 * e1 - a1 * e0;
        vf = cx * c0 + cy * c1 + cz * c2;

        const float* q = g_nt + ((size_t)b * NF + i) * 3;
        a0 = q[0]; a1 = q[1]; a2 = q[2];
        e0 = q[3]; e1 = q[4]; e2 = q[5];
        c0 = q[6]; c1 = q[7]; c2 = q[8];
        cx = a1 * e2 - a2 * e1;
        cy = a2 * e0 - a0 * e2;
        cz = a0 * e1 - a1 * e0;
        vn = cx * c0 + cy * c1 + cz * c2;
    }
    const float r0 = blockSum(vf, sred);
    const float r1 = blockSum(vn, sred);
    if (tid == 0) { g_pv[b][bx][0] = r0; g_pv[b][bx][1] = r1; }
}

// Single-thread deterministic combine of all partials into the scalar loss.
__global__ void finalize_kernel(float* __restrict__ out)
{
    float S1f = 0.0f, Syd = 0.0f, S2f = 0.0f, S2c = 0.0f, S1c = 0.0f;
    float szf[BB], sznt[BB], vfb[BB], vnb[BB];
#pragma unroll
    for (int b = 0; b < BB; b++) { szf[b] = sznt[b] = vfb[b] = vnb[b] = 0.0f; }

    for (int b = 0; b < BB; b++) {
        for (int k = 0; k < 32; k++) {
            S1f     += g_pf[b][k][0];
            szf[b]  += g_pf[b][k][1];
            sznt[b] += g_pf[b][k][2];
            Syd     += g_pf[b][k][3];
            S2f     += g_pt[b][k][0];
            S2c     += g_pt[b][k][1];
            vfb[b]  += g_pv[b][k][0];
            vnb[b]  += g_pv[b][k][1];
        }
        S1c += g_pc[b][0] + g_pc[b][1];
    }

    const float la_f = 0.5f * (S1f / (float)(BB * NF) + S2f / (float)(BB * MM));
    const float la_c = 0.5f * (S1c / (float)(BB * NC) + S2c / (float)(BB * MM));
    const float lref = Syd / (float)(BB * NF);

    float lrot = 0.0f, lgeo = 0.0f;
    for (int b = 0; b < BB; b++) {
        const float dr = sqrtf(szf[b]) - sqrtf(sznt[b]);
        lrot += dr * dr;
        const float dg = (vfb[b] - vnb[b]) * (1.0f / 6.0f);
        lgeo += dg * dg;
    }
    lrot *= (1.0f / (float)BB);
    lgeo *= (1.0f / (float)BB);

    out[0] = lrot + lref + la_c + la_f + lgeo;
}

extern "C" void kernel_launch(void* const* d_in, const int* in_sizes, int n_in,
                              void* d_out, int out_size)
{
    const float* sc = (const float*)d_in[0];  // source_coarse (B, 512, 3)
    const float* sf = (const float*)d_in[1];  // source_fine   (B, 8192, 3)
    const float* tp = (const float*)d_in[2];  // target_points (B, 8192, 3)
    float* out = (float*)d_out;

    dim3 g1(66, BB);
    nn_kernel<<<g1, NT>>>(sc, sf, tp);

    dim3 g2(32, BB);
    volume_kernel<<<g2, NT>>>(sf);

    finalize_kernel<<<1, 1>>>(out);
}